// round 8
// baseline (speedup 1.0000x reference)
#include <cuda_runtime.h>
#include <stdint.h>

// =====================================================================
// EBSW loss: JAX threefry RNG + IMH chain + sliced W2 distances
// R7: R4 sort structure (V=32, 128 thr/array) with overhead trims:
//     - direct float4 gmem->register projection (no smem staging)
//     - y-group publishes, x-group reduces from registers
//     - per-group named barriers for smem exchange phases
// =====================================================================

#define PARTITIONABLE 1

static const int BATCH = 64;
static const int NPTS  = 4096;
static const int DIMS  = 3;
static const int LPROJ = 128;

__device__ float g_theta[LPROJ][BATCH][DIMS];
__device__ float g_logu [LPROJ][BATCH];
__device__ float g_dist [BATCH][LPROJ];

// ---------------------------------------------------------------------
// threefry2x32 (20 rounds)
// ---------------------------------------------------------------------
__device__ __forceinline__ uint2 tf2x32(unsigned k0, unsigned k1,
                                        unsigned x0, unsigned x1) {
    unsigned ks2 = k0 ^ k1 ^ 0x1BD11BDAu;
    x0 += k0; x1 += k1;
#define TFR(r) { x0 += x1; x1 = (x1 << (r)) | (x1 >> (32 - (r))); x1 ^= x0; }
    TFR(13) TFR(15) TFR(26) TFR(6)
    x0 += k1; x1 += ks2 + 1u;
    TFR(17) TFR(29) TFR(16) TFR(24)
    x0 += ks2; x1 += k0 + 2u;
    TFR(13) TFR(15) TFR(26) TFR(6)
    x0 += k0; x1 += k1 + 3u;
    TFR(17) TFR(29) TFR(16) TFR(24)
    x0 += k1; x1 += ks2 + 4u;
    TFR(13) TFR(15) TFR(26) TFR(6)
    x0 += ks2; x1 += k0 + 5u;
#undef TFR
    return make_uint2(x0, x1);
}

__device__ __forceinline__ float xla_erfinv(float x) {
    float xx = __fmul_rn(x, x);
    float w  = -log1pf(-xx);
    float p;
    if (w < 5.0f) {
        w = __fadd_rn(w, -2.5f);
        p = 2.81022636e-08f;
        p = __fadd_rn( 3.43273939e-07f, __fmul_rn(p, w));
        p = __fadd_rn(-3.5233877e-06f,  __fmul_rn(p, w));
        p = __fadd_rn(-4.39150654e-06f, __fmul_rn(p, w));
        p = __fadd_rn( 0.00021858087f,  __fmul_rn(p, w));
        p = __fadd_rn(-0.00125372503f,  __fmul_rn(p, w));
        p = __fadd_rn(-0.00417768164f,  __fmul_rn(p, w));
        p = __fadd_rn( 0.246640727f,    __fmul_rn(p, w));
        p = __fadd_rn( 1.50140941f,     __fmul_rn(p, w));
    } else {
        w = __fadd_rn(__fsqrt_rn(w), -3.0f);
        p = -0.000200214257f;
        p = __fadd_rn( 0.000100950558f, __fmul_rn(p, w));
        p = __fadd_rn( 0.00134934322f,  __fmul_rn(p, w));
        p = __fadd_rn(-0.00367342844f,  __fmul_rn(p, w));
        p = __fadd_rn( 0.00573950773f,  __fmul_rn(p, w));
        p = __fadd_rn(-0.0076224613f,   __fmul_rn(p, w));
        p = __fadd_rn( 0.00943887047f,  __fmul_rn(p, w));
        p = __fadd_rn( 1.00167406f,     __fmul_rn(p, w));
        p = __fadd_rn( 2.83297682f,     __fmul_rn(p, w));
    }
    return __fmul_rn(p, x);
}

__device__ __forceinline__ float bits_to_unit(unsigned bits) {
    return __uint_as_float((bits >> 9) | 0x3f800000u) - 1.0f;
}

// ---------------------------------------------------------------------
// RNG kernel (unchanged — bit-exact, ~5us)
// ---------------------------------------------------------------------
__global__ void ebsw_rng_kernel() {
    const int l = blockIdx.x;
    const int t = threadIdx.x;
    __shared__ float raw[BATCH * DIMS];

    uint2 kl = tf2x32(0u, 42u, 0u, (unsigned)l);
    uint2 ka, kb;
    if (l == 0) {
        ka = kl; kb = make_uint2(0u, 0u);
    } else {
#if PARTITIONABLE
        ka = tf2x32(kl.x, kl.y, 0u, 0u);
        kb = tf2x32(kl.x, kl.y, 0u, 1u);
#else
        uint2 p0 = tf2x32(kl.x, kl.y, 0u, 2u);
        uint2 p1 = tf2x32(kl.x, kl.y, 1u, 3u);
        ka = make_uint2(p0.x, p1.x);
        kb = make_uint2(p0.y, p1.y);
#endif
    }

    unsigned bits;
#if PARTITIONABLE
    { uint2 r = tf2x32(ka.x, ka.y, 0u, (unsigned)t); bits = r.x ^ r.y; }
#else
    if (t < 96) { uint2 r = tf2x32(ka.x, ka.y, (unsigned)t, (unsigned)(96 + t)); bits = r.x; }
    else        { uint2 r = tf2x32(ka.x, ka.y, (unsigned)(t - 96), (unsigned)t); bits = r.y; }
#endif
    const float LO = -0.99999994f;
    float f = bits_to_unit(bits);
    float u = __fadd_rn(__fmul_rn(f, 2.0f), LO);
    u = fmaxf(LO, u);
    raw[t] = __fmul_rn(1.41421356237309515f, xla_erfinv(u));
    __syncthreads();

    if (t < BATCH) {
        float v0 = raw[t * 3 + 0], v1 = raw[t * 3 + 1], v2 = raw[t * 3 + 2];
        float s  = __fadd_rn(__fadd_rn(__fmul_rn(v0, v0), __fmul_rn(v1, v1)),
                             __fmul_rn(v2, v2));
        float r  = __fsqrt_rn(s);
        g_theta[l][t][0] = __fdiv_rn(v0, r);
        g_theta[l][t][1] = __fdiv_rn(v1, r);
        g_theta[l][t][2] = __fdiv_rn(v2, r);

        if (l >= 1) {
            unsigned ub;
#if PARTITIONABLE
            { uint2 r2 = tf2x32(kb.x, kb.y, 0u, (unsigned)t); ub = r2.x ^ r2.y; }
#else
            if (t < 32) { uint2 r2 = tf2x32(kb.x, kb.y, (unsigned)t, (unsigned)(32 + t)); ub = r2.x; }
            else        { uint2 r2 = tf2x32(kb.x, kb.y, (unsigned)(t - 32), (unsigned)t); ub = r2.y; }
#endif
            g_logu[l][t] = logf(bits_to_unit(ub));
        }
    }
}

// ---------------------------------------------------------------------
// Distance kernel: V=32 elems/thread, 128 threads/array, 256 thr/CTA
// ---------------------------------------------------------------------
static const int TPB = 256;
static const int TPA = 128;    // threads per array
static const int V   = 32;     // elements per thread
static const int PAD = 33;     // padded row stride (conflict-free)

// per-group named barrier (128 threads = 4 whole warps)
__device__ __forceinline__ void barg(int id) {
    asm volatile("bar.sync %0, %1;" :: "r"(id), "r"(TPA) : "memory");
}

__device__ __forceinline__ void cx(float& a, float& b, bool up) {
    float lo = up ? fminf(a, b) : fmaxf(a, b);
    float hi = up ? fmaxf(a, b) : fminf(a, b);
    a = lo; b = hi;
}

template<int J>
__device__ __forceinline__ void merge_reg(float* r, bool up) {
    if constexpr (J >= 1) {
#pragma unroll
        for (int v = 0; v < V; ++v)
            if ((v & J) == 0) cx(r[v], r[v | J], up);
        merge_reg<J / 2>(r, up);
    }
}

template<int K, int J>
__device__ __forceinline__ void sort_reg_small(float* r) {
    if constexpr (J >= 1) {
#pragma unroll
        for (int v = 0; v < V; ++v)
            if ((v & J) == 0) cx(r[v], r[v | J], ((v & K) == 0));
        sort_reg_small<K, J / 2>(r);
    }
}

template<int D>
__device__ __forceinline__ void exchange_step(float* r, float* buf, int lt,
                                              bool up, int barid) {
    const bool keepmin = (((lt & D) == 0) == up);
    if constexpr (D < 32) {
#pragma unroll
        for (int v = 0; v < V; ++v) {
            float o = __shfl_xor_sync(0xffffffffu, r[v], D);
            r[v] = keepmin ? fminf(r[v], o) : fmaxf(r[v], o);
        }
    } else {
#pragma unroll
        for (int v = 0; v < V; ++v) buf[lt * PAD + v] = r[v];
        barg(barid);
        const int p = (lt ^ D) * PAD;
#pragma unroll
        for (int v = 0; v < V; ++v) {
            float o = buf[p + v];
            r[v] = keepmin ? fminf(r[v], o) : fmaxf(r[v], o);
        }
        barg(barid);
    }
}

template<int D>
__device__ __forceinline__ void merge_chain(float* r, float* buf, int lt,
                                            bool up, int barid) {
    if constexpr (D >= 1) {
        exchange_step<D>(r, buf, lt, up, barid);
        merge_chain<D / 2>(r, buf, lt, up, barid);
    } else {
        merge_reg<V / 2>(r, up);
    }
}

__global__ __launch_bounds__(TPB) void ebsw_dist_kernel(
        const float* __restrict__ x, const float* __restrict__ y) {
    __shared__ float s[2 * TPA * PAD];   // exchange buffers, one half per group
    __shared__ double wsum[TPA / 32];
    const int blk = blockIdx.x;
    const int b = blk >> 7;
    const int l = blk & (LPROJ - 1);

    const float t0 = g_theta[l][b][0];
    const float t1 = g_theta[l][b][1];
    const float t2 = g_theta[l][b][2];

    const int tid = threadIdx.x;
    const int g   = tid >> 7;          // 0 -> x array, 1 -> y array
    const int lt  = tid & (TPA - 1);   // 0..127 within group
    const int barid = g + 1;           // named barrier 1 or 2
    float* buf = s + g * (TPA * PAD);

    // Direct gmem->register projection: thread owns points lt*32..lt*32+31,
    // i.e. 96 contiguous floats = 24 float4 loads (16B-aligned: lt*384B).
    float r[V];
    {
        const float4* pb4 = (const float4*)(((g == 0) ? x : y)
                          + (size_t)b * NPTS * DIMS + (size_t)lt * V * DIMS);
#pragma unroll
        for (int j = 0; j < V / 4; ++j) {
            float4 f0 = pb4[j * 3 + 0];
            float4 f1 = pb4[j * 3 + 1];
            float4 f2 = pb4[j * 3 + 2];
            r[4 * j + 0] = fmaf(f0.x, t0, fmaf(f0.y, t1, f0.z * t2));
            r[4 * j + 1] = fmaf(f0.w, t0, fmaf(f1.x, t1, f1.y * t2));
            r[4 * j + 2] = fmaf(f1.z, t0, fmaf(f1.w, t1, f2.x * t2));
            r[4 * j + 3] = fmaf(f2.y, t0, fmaf(f2.z, t1, f2.w * t2));
        }
    }

    // ---- bitonic sort of 4096 = 128 threads x 32 regs ----
    sort_reg_small<2, 1>(r);
    sort_reg_small<4, 2>(r);
    sort_reg_small<8, 4>(r);
    sort_reg_small<16, 8>(r);
    { bool up = ((lt & 1)  == 0); merge_reg<V / 2>(r, up); }                  // k=32
    { bool up = ((lt & 2)  == 0); merge_chain<1 >(r, buf, lt, up, barid); }   // k=64
    { bool up = ((lt & 4)  == 0); merge_chain<2 >(r, buf, lt, up, barid); }   // k=128
    { bool up = ((lt & 8)  == 0); merge_chain<4 >(r, buf, lt, up, barid); }   // k=256
    { bool up = ((lt & 16) == 0); merge_chain<8 >(r, buf, lt, up, barid); }   // k=512
    { bool up = ((lt & 32) == 0); merge_chain<16>(r, buf, lt, up, barid); }   // k=1024
    { bool up = ((lt & 64) == 0); merge_chain<32>(r, buf, lt, up, barid); }   // k=2048
    {                             merge_chain<64>(r, buf, lt, true, barid); } // k=4096

    // ---- final reduce: y-group publishes, x-group diffs from registers ----
    if (g == 1) {
#pragma unroll
        for (int v = 0; v < V; ++v) buf[lt * PAD + v] = r[v];
    }
    __syncthreads();   // y sorted values visible to x-group

    if (g == 0) {
        const float* by = s + TPA * PAD + lt * PAD;
        double acc = 0.0;
#pragma unroll
        for (int v = 0; v < V; ++v) {
            float d = r[v] - by[v];
            acc += (double)d * (double)d;
        }
#pragma unroll
        for (int off = 16; off; off >>= 1)
            acc += __shfl_down_sync(0xffffffffu, acc, off);
        if ((lt & 31) == 0) wsum[lt >> 5] = acc;
    }
    __syncthreads();
    if (tid == 0)
        g_dist[b][l] = (float)(wsum[0] + wsum[1] + wsum[2] + wsum[3]);
}

// ---------------------------------------------------------------------
// Chain + loss kernel (unchanged)
// ---------------------------------------------------------------------
__global__ void ebsw_chain_kernel(float* __restrict__ out) {
    const int b = threadIdx.x;
    __shared__ double sh[BATCH];
    const float* db = g_dist[b];
    float dist_old = db[0];
    double acc = (double)dist_old;
    for (int l = 1; l < LPROJ; ++l) {
        float dn = db[l];
        float ar = fminf(0.0f, __fadd_rn(dn, -dist_old));
        if (g_logu[l][b] <= ar) dist_old = dn;
        acc += (double)dist_old;
    }
    sh[b] = sqrt(acc / (double)LPROJ);
    __syncthreads();
    if (b == 0) {
        double ssum = 0.0;
        for (int i = 0; i < BATCH; ++i) ssum += sh[i];
        out[0] = (float)(ssum / (double)BATCH);
    }
}

// ---------------------------------------------------------------------
extern "C" void kernel_launch(void* const* d_in, const int* in_sizes, int n_in,
                              void* d_out, int out_size) {
    const float* x = (const float*)d_in[0];
    const float* y = (const float*)d_in[1];
    float* out = (float*)d_out;

    ebsw_rng_kernel<<<LPROJ, BATCH * DIMS>>>();
    ebsw_dist_kernel<<<BATCH * LPROJ, TPB>>>(x, y);
    ebsw_chain_kernel<<<1, BATCH>>>(out);
}

// round 9
// speedup vs baseline: 1.2054x; 1.2054x over previous
#include <cuda_runtime.h>
#include <stdint.h>

// =====================================================================
// EBSW loss: JAX threefry RNG + IMH chain + sliced W2 distances
// R9: R4 structure (V=32, 128 thr/array, coalesced smem staging) +
//     per-group named barriers + y-publish/x-register-reduce ending.
// =====================================================================

#define PARTITIONABLE 1

static const int BATCH = 64;
static const int NPTS  = 4096;
static const int DIMS  = 3;
static const int LPROJ = 128;

__device__ float g_theta[LPROJ][BATCH][DIMS];
__device__ float g_logu [LPROJ][BATCH];
__device__ float g_dist [BATCH][LPROJ];

// ---------------------------------------------------------------------
// threefry2x32 (20 rounds)
// ---------------------------------------------------------------------
__device__ __forceinline__ uint2 tf2x32(unsigned k0, unsigned k1,
                                        unsigned x0, unsigned x1) {
    unsigned ks2 = k0 ^ k1 ^ 0x1BD11BDAu;
    x0 += k0; x1 += k1;
#define TFR(r) { x0 += x1; x1 = (x1 << (r)) | (x1 >> (32 - (r))); x1 ^= x0; }
    TFR(13) TFR(15) TFR(26) TFR(6)
    x0 += k1; x1 += ks2 + 1u;
    TFR(17) TFR(29) TFR(16) TFR(24)
    x0 += ks2; x1 += k0 + 2u;
    TFR(13) TFR(15) TFR(26) TFR(6)
    x0 += k0; x1 += k1 + 3u;
    TFR(17) TFR(29) TFR(16) TFR(24)
    x0 += k1; x1 += ks2 + 4u;
    TFR(13) TFR(15) TFR(26) TFR(6)
    x0 += ks2; x1 += k0 + 5u;
#undef TFR
    return make_uint2(x0, x1);
}

__device__ __forceinline__ float xla_erfinv(float x) {
    float xx = __fmul_rn(x, x);
    float w  = -log1pf(-xx);
    float p;
    if (w < 5.0f) {
        w = __fadd_rn(w, -2.5f);
        p = 2.81022636e-08f;
        p = __fadd_rn( 3.43273939e-07f, __fmul_rn(p, w));
        p = __fadd_rn(-3.5233877e-06f,  __fmul_rn(p, w));
        p = __fadd_rn(-4.39150654e-06f, __fmul_rn(p, w));
        p = __fadd_rn( 0.00021858087f,  __fmul_rn(p, w));
        p = __fadd_rn(-0.00125372503f,  __fmul_rn(p, w));
        p = __fadd_rn(-0.00417768164f,  __fmul_rn(p, w));
        p = __fadd_rn( 0.246640727f,    __fmul_rn(p, w));
        p = __fadd_rn( 1.50140941f,     __fmul_rn(p, w));
    } else {
        w = __fadd_rn(__fsqrt_rn(w), -3.0f);
        p = -0.000200214257f;
        p = __fadd_rn( 0.000100950558f, __fmul_rn(p, w));
        p = __fadd_rn( 0.00134934322f,  __fmul_rn(p, w));
        p = __fadd_rn(-0.00367342844f,  __fmul_rn(p, w));
        p = __fadd_rn( 0.00573950773f,  __fmul_rn(p, w));
        p = __fadd_rn(-0.0076224613f,   __fmul_rn(p, w));
        p = __fadd_rn( 0.00943887047f,  __fmul_rn(p, w));
        p = __fadd_rn( 1.00167406f,     __fmul_rn(p, w));
        p = __fadd_rn( 2.83297682f,     __fmul_rn(p, w));
    }
    return __fmul_rn(p, x);
}

__device__ __forceinline__ float bits_to_unit(unsigned bits) {
    return __uint_as_float((bits >> 9) | 0x3f800000u) - 1.0f;
}

// ---------------------------------------------------------------------
// RNG kernel (unchanged — bit-exact, ~5us)
// ---------------------------------------------------------------------
__global__ void ebsw_rng_kernel() {
    const int l = blockIdx.x;
    const int t = threadIdx.x;
    __shared__ float raw[BATCH * DIMS];

    uint2 kl = tf2x32(0u, 42u, 0u, (unsigned)l);
    uint2 ka, kb;
    if (l == 0) {
        ka = kl; kb = make_uint2(0u, 0u);
    } else {
#if PARTITIONABLE
        ka = tf2x32(kl.x, kl.y, 0u, 0u);
        kb = tf2x32(kl.x, kl.y, 0u, 1u);
#else
        uint2 p0 = tf2x32(kl.x, kl.y, 0u, 2u);
        uint2 p1 = tf2x32(kl.x, kl.y, 1u, 3u);
        ka = make_uint2(p0.x, p1.x);
        kb = make_uint2(p0.y, p1.y);
#endif
    }

    unsigned bits;
#if PARTITIONABLE
    { uint2 r = tf2x32(ka.x, ka.y, 0u, (unsigned)t); bits = r.x ^ r.y; }
#else
    if (t < 96) { uint2 r = tf2x32(ka.x, ka.y, (unsigned)t, (unsigned)(96 + t)); bits = r.x; }
    else        { uint2 r = tf2x32(ka.x, ka.y, (unsigned)(t - 96), (unsigned)t); bits = r.y; }
#endif
    const float LO = -0.99999994f;
    float f = bits_to_unit(bits);
    float u = __fadd_rn(__fmul_rn(f, 2.0f), LO);
    u = fmaxf(LO, u);
    raw[t] = __fmul_rn(1.41421356237309515f, xla_erfinv(u));
    __syncthreads();

    if (t < BATCH) {
        float v0 = raw[t * 3 + 0], v1 = raw[t * 3 + 1], v2 = raw[t * 3 + 2];
        float s  = __fadd_rn(__fadd_rn(__fmul_rn(v0, v0), __fmul_rn(v1, v1)),
                             __fmul_rn(v2, v2));
        float r  = __fsqrt_rn(s);
        g_theta[l][t][0] = __fdiv_rn(v0, r);
        g_theta[l][t][1] = __fdiv_rn(v1, r);
        g_theta[l][t][2] = __fdiv_rn(v2, r);

        if (l >= 1) {
            unsigned ub;
#if PARTITIONABLE
            { uint2 r2 = tf2x32(kb.x, kb.y, 0u, (unsigned)t); ub = r2.x ^ r2.y; }
#else
            if (t < 32) { uint2 r2 = tf2x32(kb.x, kb.y, (unsigned)t, (unsigned)(32 + t)); ub = r2.x; }
            else        { uint2 r2 = tf2x32(kb.x, kb.y, (unsigned)(t - 32), (unsigned)t); ub = r2.y; }
#endif
            g_logu[l][t] = logf(bits_to_unit(ub));
        }
    }
}

// ---------------------------------------------------------------------
// Distance kernel: V=32 elems/thread, 128 threads/array, 256 thr/CTA
// ---------------------------------------------------------------------
static const int TPB = 256;
static const int TPA = 128;    // threads per array
static const int V   = 32;     // elements per thread
static const int PAD = 33;     // padded row stride (conflict-free)

// per-group named barrier (128 threads = 4 whole warps)
__device__ __forceinline__ void barg(int id) {
    asm volatile("bar.sync %0, %1;" :: "r"(id), "r"(TPA) : "memory");
}

__device__ __forceinline__ void cx(float& a, float& b, bool up) {
    float lo = up ? fminf(a, b) : fmaxf(a, b);
    float hi = up ? fmaxf(a, b) : fminf(a, b);
    a = lo; b = hi;
}

template<int J>
__device__ __forceinline__ void merge_reg(float* r, bool up) {
    if constexpr (J >= 1) {
#pragma unroll
        for (int v = 0; v < V; ++v)
            if ((v & J) == 0) cx(r[v], r[v | J], up);
        merge_reg<J / 2>(r, up);
    }
}

template<int K, int J>
__device__ __forceinline__ void sort_reg_small(float* r) {
    if constexpr (J >= 1) {
#pragma unroll
        for (int v = 0; v < V; ++v)
            if ((v & J) == 0) cx(r[v], r[v | J], ((v & K) == 0));
        sort_reg_small<K, J / 2>(r);
    }
}

template<int D>
__device__ __forceinline__ void exchange_step(float* r, float* buf, int lt,
                                              bool up, int barid) {
    const bool keepmin = (((lt & D) == 0) == up);
    if constexpr (D < 32) {
#pragma unroll
        for (int v = 0; v < V; ++v) {
            float o = __shfl_xor_sync(0xffffffffu, r[v], D);
            r[v] = keepmin ? fminf(r[v], o) : fmaxf(r[v], o);
        }
    } else {
#pragma unroll
        for (int v = 0; v < V; ++v) buf[lt * PAD + v] = r[v];
        barg(barid);
        const int p = (lt ^ D) * PAD;
#pragma unroll
        for (int v = 0; v < V; ++v) {
            float o = buf[p + v];
            r[v] = keepmin ? fminf(r[v], o) : fmaxf(r[v], o);
        }
        barg(barid);
    }
}

template<int D>
__device__ __forceinline__ void merge_chain(float* r, float* buf, int lt,
                                            bool up, int barid) {
    if constexpr (D >= 1) {
        exchange_step<D>(r, buf, lt, up, barid);
        merge_chain<D / 2>(r, buf, lt, up, barid);
    } else {
        merge_reg<V / 2>(r, up);
    }
}

__global__ __launch_bounds__(TPB) void ebsw_dist_kernel(
        const float* __restrict__ x, const float* __restrict__ y) {
    __shared__ float s[2 * TPA * PAD];   // staging/exchange, one half per group
    __shared__ double wsum[TPA / 32];
    const int blk = blockIdx.x;
    const int b = blk >> 7;
    const int l = blk & (LPROJ - 1);

    const float t0 = g_theta[l][b][0];
    const float t1 = g_theta[l][b][1];
    const float t2 = g_theta[l][b][2];

    const int tid = threadIdx.x;
    const int g   = tid >> 7;          // 0 -> x array, 1 -> y array
    const int lt  = tid & (TPA - 1);   // 0..127 within group
    const int barid = g + 1;           // named barrier 1 or 2
    float* buf = s + g * (TPA * PAD);

    // Coalesced projection staging (strided->blocked transpose via smem)
    const float* pb = (g == 0 ? x : y) + (size_t)b * NPTS * DIMS;
    for (int n = lt; n < NPTS; n += TPA) {
        int o = n * 3;
        buf[(n >> 5) * PAD + (n & 31)] =
            fmaf(pb[o], t0, fmaf(pb[o + 1], t1, pb[o + 2] * t2));
    }
    barg(barid);

    // Load 32 contiguous elements into registers: i = lt*32 + v
    float r[V];
#pragma unroll
    for (int v = 0; v < V; ++v) r[v] = buf[lt * PAD + v];
    barg(barid);

    // ---- bitonic sort of 4096 = 128 threads x 32 regs ----
    sort_reg_small<2, 1>(r);
    sort_reg_small<4, 2>(r);
    sort_reg_small<8, 4>(r);
    sort_reg_small<16, 8>(r);
    { bool up = ((lt & 1)  == 0); merge_reg<V / 2>(r, up); }                  // k=32
    { bool up = ((lt & 2)  == 0); merge_chain<1 >(r, buf, lt, up, barid); }   // k=64
    { bool up = ((lt & 4)  == 0); merge_chain<2 >(r, buf, lt, up, barid); }   // k=128
    { bool up = ((lt & 8)  == 0); merge_chain<4 >(r, buf, lt, up, barid); }   // k=256
    { bool up = ((lt & 16) == 0); merge_chain<8 >(r, buf, lt, up, barid); }   // k=512
    { bool up = ((lt & 32) == 0); merge_chain<16>(r, buf, lt, up, barid); }   // k=1024
    { bool up = ((lt & 64) == 0); merge_chain<32>(r, buf, lt, up, barid); }   // k=2048
    {                             merge_chain<64>(r, buf, lt, true, barid); } // k=4096

    // ---- final reduce: y-group publishes, x-group diffs from registers ----
    if (g == 1) {
#pragma unroll
        for (int v = 0; v < V; ++v) buf[lt * PAD + v] = r[v];
    }
    __syncthreads();   // y sorted values visible to x-group

    if (g == 0) {
        const float* by = s + TPA * PAD + lt * PAD;
        double acc = 0.0;
#pragma unroll
        for (int v = 0; v < V; ++v) {
            float d = r[v] - by[v];
            acc += (double)d * (double)d;
        }
#pragma unroll
        for (int off = 16; off; off >>= 1)
            acc += __shfl_down_sync(0xffffffffu, acc, off);
        if ((lt & 31) == 0) wsum[lt >> 5] = acc;
    }
    __syncthreads();
    if (tid == 0)
        g_dist[b][l] = (float)(wsum[0] + wsum[1] + wsum[2] + wsum[3]);
}

// ---------------------------------------------------------------------
// Chain + loss kernel (unchanged)
// ---------------------------------------------------------------------
__global__ void ebsw_chain_kernel(float* __restrict__ out) {
    const int b = threadIdx.x;
    __shared__ double sh[BATCH];
    const float* db = g_dist[b];
    float dist_old = db[0];
    double acc = (double)dist_old;
    for (int l = 1; l < LPROJ; ++l) {
        float dn = db[l];
        float ar = fminf(0.0f, __fadd_rn(dn, -dist_old));
        if (g_logu[l][b] <= ar) dist_old = dn;
        acc += (double)dist_old;
    }
    sh[b] = sqrt(acc / (double)LPROJ);
    __syncthreads();
    if (b == 0) {
        double ssum = 0.0;
        for (int i = 0; i < BATCH; ++i) ssum += sh[i];
        out[0] = (float)(ssum / (double)BATCH);
    }
}

// ---------------------------------------------------------------------
extern "C" void kernel_launch(void* const* d_in, const int* in_sizes, int n_in,
                              void* d_out, int out_size) {
    const float* x = (const float*)d_in[0];
    const float* y = (const float*)d_in[1];
    float* out = (float*)d_out;

    ebsw_rng_kernel<<<LPROJ, BATCH * DIMS>>>();
    ebsw_dist_kernel<<<BATCH * LPROJ, TPB>>>(x, y);
    ebsw_chain_kernel<<<1, BATCH>>>(out);
}

// round 10
// speedup vs baseline: 1.3287x; 1.1023x over previous
#include <cuda_runtime.h>
#include <stdint.h>

// =====================================================================
// EBSW loss: JAX threefry RNG + IMH chain + sliced W2 distances
// R10: direction-free bitonic. Intra-thread phases use compile-time
//      operand swaps; runtime-direction merges use the sign-negation
//      trick so every comparator is a fixed ascending min/max pair.
// =====================================================================

#define PARTITIONABLE 1

static const int BATCH = 64;
static const int NPTS  = 4096;
static const int DIMS  = 3;
static const int LPROJ = 128;

__device__ float g_theta[LPROJ][BATCH][DIMS];
__device__ float g_logu [LPROJ][BATCH];
__device__ float g_dist [BATCH][LPROJ];

// ---------------------------------------------------------------------
// threefry2x32 (20 rounds)
// ---------------------------------------------------------------------
__device__ __forceinline__ uint2 tf2x32(unsigned k0, unsigned k1,
                                        unsigned x0, unsigned x1) {
    unsigned ks2 = k0 ^ k1 ^ 0x1BD11BDAu;
    x0 += k0; x1 += k1;
#define TFR(r) { x0 += x1; x1 = (x1 << (r)) | (x1 >> (32 - (r))); x1 ^= x0; }
    TFR(13) TFR(15) TFR(26) TFR(6)
    x0 += k1; x1 += ks2 + 1u;
    TFR(17) TFR(29) TFR(16) TFR(24)
    x0 += ks2; x1 += k0 + 2u;
    TFR(13) TFR(15) TFR(26) TFR(6)
    x0 += k0; x1 += k1 + 3u;
    TFR(17) TFR(29) TFR(16) TFR(24)
    x0 += k1; x1 += ks2 + 4u;
    TFR(13) TFR(15) TFR(26) TFR(6)
    x0 += ks2; x1 += k0 + 5u;
#undef TFR
    return make_uint2(x0, x1);
}

__device__ __forceinline__ float xla_erfinv(float x) {
    float xx = __fmul_rn(x, x);
    float w  = -log1pf(-xx);
    float p;
    if (w < 5.0f) {
        w = __fadd_rn(w, -2.5f);
        p = 2.81022636e-08f;
        p = __fadd_rn( 3.43273939e-07f, __fmul_rn(p, w));
        p = __fadd_rn(-3.5233877e-06f,  __fmul_rn(p, w));
        p = __fadd_rn(-4.39150654e-06f, __fmul_rn(p, w));
        p = __fadd_rn( 0.00021858087f,  __fmul_rn(p, w));
        p = __fadd_rn(-0.00125372503f,  __fmul_rn(p, w));
        p = __fadd_rn(-0.00417768164f,  __fmul_rn(p, w));
        p = __fadd_rn( 0.246640727f,    __fmul_rn(p, w));
        p = __fadd_rn( 1.50140941f,     __fmul_rn(p, w));
    } else {
        w = __fadd_rn(__fsqrt_rn(w), -3.0f);
        p = -0.000200214257f;
        p = __fadd_rn( 0.000100950558f, __fmul_rn(p, w));
        p = __fadd_rn( 0.00134934322f,  __fmul_rn(p, w));
        p = __fadd_rn(-0.00367342844f,  __fmul_rn(p, w));
        p = __fadd_rn( 0.00573950773f,  __fmul_rn(p, w));
        p = __fadd_rn(-0.0076224613f,   __fmul_rn(p, w));
        p = __fadd_rn( 0.00943887047f,  __fmul_rn(p, w));
        p = __fadd_rn( 1.00167406f,     __fmul_rn(p, w));
        p = __fadd_rn( 2.83297682f,     __fmul_rn(p, w));
    }
    return __fmul_rn(p, x);
}

__device__ __forceinline__ float bits_to_unit(unsigned bits) {
    return __uint_as_float((bits >> 9) | 0x3f800000u) - 1.0f;
}

// ---------------------------------------------------------------------
// RNG kernel (unchanged — bit-exact, ~5us)
// ---------------------------------------------------------------------
__global__ void ebsw_rng_kernel() {
    const int l = blockIdx.x;
    const int t = threadIdx.x;
    __shared__ float raw[BATCH * DIMS];

    uint2 kl = tf2x32(0u, 42u, 0u, (unsigned)l);
    uint2 ka, kb;
    if (l == 0) {
        ka = kl; kb = make_uint2(0u, 0u);
    } else {
#if PARTITIONABLE
        ka = tf2x32(kl.x, kl.y, 0u, 0u);
        kb = tf2x32(kl.x, kl.y, 0u, 1u);
#else
        uint2 p0 = tf2x32(kl.x, kl.y, 0u, 2u);
        uint2 p1 = tf2x32(kl.x, kl.y, 1u, 3u);
        ka = make_uint2(p0.x, p1.x);
        kb = make_uint2(p0.y, p1.y);
#endif
    }

    unsigned bits;
#if PARTITIONABLE
    { uint2 r = tf2x32(ka.x, ka.y, 0u, (unsigned)t); bits = r.x ^ r.y; }
#else
    if (t < 96) { uint2 r = tf2x32(ka.x, ka.y, (unsigned)t, (unsigned)(96 + t)); bits = r.x; }
    else        { uint2 r = tf2x32(ka.x, ka.y, (unsigned)(t - 96), (unsigned)t); bits = r.y; }
#endif
    const float LO = -0.99999994f;
    float f = bits_to_unit(bits);
    float u = __fadd_rn(__fmul_rn(f, 2.0f), LO);
    u = fmaxf(LO, u);
    raw[t] = __fmul_rn(1.41421356237309515f, xla_erfinv(u));
    __syncthreads();

    if (t < BATCH) {
        float v0 = raw[t * 3 + 0], v1 = raw[t * 3 + 1], v2 = raw[t * 3 + 2];
        float s  = __fadd_rn(__fadd_rn(__fmul_rn(v0, v0), __fmul_rn(v1, v1)),
                             __fmul_rn(v2, v2));
        float r  = __fsqrt_rn(s);
        g_theta[l][t][0] = __fdiv_rn(v0, r);
        g_theta[l][t][1] = __fdiv_rn(v1, r);
        g_theta[l][t][2] = __fdiv_rn(v2, r);

        if (l >= 1) {
            unsigned ub;
#if PARTITIONABLE
            { uint2 r2 = tf2x32(kb.x, kb.y, 0u, (unsigned)t); ub = r2.x ^ r2.y; }
#else
            if (t < 32) { uint2 r2 = tf2x32(kb.x, kb.y, (unsigned)t, (unsigned)(32 + t)); ub = r2.x; }
            else        { uint2 r2 = tf2x32(kb.x, kb.y, (unsigned)(t - 32), (unsigned)t); ub = r2.y; }
#endif
            g_logu[l][t] = logf(bits_to_unit(ub));
        }
    }
}

// ---------------------------------------------------------------------
// Distance kernel: V=32 elems/thread, 128 threads/array, 256 thr/CTA
// ---------------------------------------------------------------------
static const int TPB = 256;
static const int TPA = 128;    // threads per array
static const int V   = 32;     // elements per thread
static const int PAD = 33;     // padded row stride (conflict-free)

// per-group named barrier (128 threads = 4 whole warps)
__device__ __forceinline__ void barg(int id) {
    asm volatile("bar.sync %0, %1;" :: "r"(id), "r"(TPA) : "memory");
}

// fixed ascending compare-exchange: min -> a, max -> b (2 FMNMX, no predicate)
__device__ __forceinline__ void cxa(float& a, float& b) {
    float mn = fminf(a, b);
    float mx = fmaxf(a, b);
    a = mn; b = mx;
}

// ascending intra-register merge, strides J..1
template<int J>
__device__ __forceinline__ void merge_reg_asc(float* r) {
    if constexpr (J >= 1) {
#pragma unroll
        for (int v = 0; v < V; ++v)
            if ((v & J) == 0) cxa(r[v], r[v | J]);
        merge_reg_asc<J / 2>(r);
    }
}

// intra-register sort phase for block size K<=16; direction (v&K)==0 is
// compile-time under full unroll -> descending = operand-swapped ascending
template<int K, int J>
__device__ __forceinline__ void sort_reg_small(float* r) {
    if constexpr (J >= 1) {
#pragma unroll
        for (int v = 0; v < V; ++v) {
            if ((v & J) == 0) {
                if ((v & K) == 0) cxa(r[v], r[v | J]);
                else              cxa(r[v | J], r[v]);
            }
        }
        sort_reg_small<K, J / 2>(r);
    }
}

// ascending cross-thread exchange at distance D
template<int D>
__device__ __forceinline__ void exchange_asc(float* r, float* buf, int lt, int barid) {
    const bool keepmin = ((lt & D) == 0);
    if constexpr (D < 32) {
#pragma unroll
        for (int v = 0; v < V; ++v) {
            float o = __shfl_xor_sync(0xffffffffu, r[v], D);
            r[v] = keepmin ? fminf(r[v], o) : fmaxf(r[v], o);
        }
    } else {
#pragma unroll
        for (int v = 0; v < V; ++v) buf[lt * PAD + v] = r[v];
        barg(barid);
        const int p = (lt ^ D) * PAD;
#pragma unroll
        for (int v = 0; v < V; ++v) {
            float o = buf[p + v];
            r[v] = keepmin ? fminf(r[v], o) : fmaxf(r[v], o);
        }
        barg(barid);
    }
}

template<int D>
__device__ __forceinline__ void merge_chain_asc(float* r, float* buf, int lt, int barid) {
    if constexpr (D >= 1) {
        exchange_asc<D>(r, buf, lt, barid);
        merge_chain_asc<D / 2>(r, buf, lt, barid);
    } else {
        merge_reg_asc<V / 2>(r);
    }
}

// set negation state: XOR sign bits with mask (0 when no change) — branch-free
__device__ __forceinline__ void setneg(float* r, bool want, bool& cur) {
    unsigned m = (cur != want) ? 0x80000000u : 0u;
#pragma unroll
    for (int v = 0; v < V; ++v)
        r[v] = __uint_as_float(__float_as_uint(r[v]) ^ m);
    cur = want;
}

__global__ __launch_bounds__(TPB) void ebsw_dist_kernel(
        const float* __restrict__ x, const float* __restrict__ y) {
    __shared__ float s[2 * TPA * PAD];   // staging/exchange, one half per group
    __shared__ double wsum[TPA / 32];
    const int blk = blockIdx.x;
    const int b = blk >> 7;
    const int l = blk & (LPROJ - 1);

    const float t0 = g_theta[l][b][0];
    const float t1 = g_theta[l][b][1];
    const float t2 = g_theta[l][b][2];

    const int tid = threadIdx.x;
    const int g   = tid >> 7;          // 0 -> x array, 1 -> y array
    const int lt  = tid & (TPA - 1);   // 0..127 within group
    const int barid = g + 1;           // named barrier 1 or 2
    float* buf = s + g * (TPA * PAD);

    // Coalesced projection staging (strided->blocked transpose via smem)
    const float* pb = (g == 0 ? x : y) + (size_t)b * NPTS * DIMS;
    for (int n = lt; n < NPTS; n += TPA) {
        int o = n * 3;
        buf[(n >> 5) * PAD + (n & 31)] =
            fmaf(pb[o], t0, fmaf(pb[o + 1], t1, pb[o + 2] * t2));
    }
    barg(barid);

    // Load 32 contiguous elements into registers: i = lt*32 + v
    float r[V];
#pragma unroll
    for (int v = 0; v < V; ++v) r[v] = buf[lt * PAD + v];
    barg(barid);

    // ---- bitonic sort, direction-free comparators ----
    // k = 2..16: compile-time directions via operand swap
    sort_reg_small<2, 1>(r);
    sort_reg_small<4, 2>(r);
    sort_reg_small<8, 4>(r);
    sort_reg_small<16, 8>(r);
    // k = 32..4096: runtime direction folded into sign negation.
    // merge k has up = ((lt & (k>>5)) == 0); we want neg = !up.
    bool neg = false;
    setneg(r, (lt & 1)  != 0, neg); merge_reg_asc<V / 2>(r);              // k=32
    setneg(r, (lt & 2)  != 0, neg); merge_chain_asc<1 >(r, buf, lt, barid); // k=64
    setneg(r, (lt & 4)  != 0, neg); merge_chain_asc<2 >(r, buf, lt, barid); // k=128
    setneg(r, (lt & 8)  != 0, neg); merge_chain_asc<4 >(r, buf, lt, barid); // k=256
    setneg(r, (lt & 16) != 0, neg); merge_chain_asc<8 >(r, buf, lt, barid); // k=512
    setneg(r, (lt & 32) != 0, neg); merge_chain_asc<16>(r, buf, lt, barid); // k=1024
    setneg(r, (lt & 64) != 0, neg); merge_chain_asc<32>(r, buf, lt, barid); // k=2048
    setneg(r, false,          neg); merge_chain_asc<64>(r, buf, lt, barid); // k=4096
    // neg == false here: registers hold exact original values, fully sorted.

    // ---- final reduce: y-group publishes, x-group diffs from registers ----
    if (g == 1) {
#pragma unroll
        for (int v = 0; v < V; ++v) buf[lt * PAD + v] = r[v];
    }
    __syncthreads();   // y sorted values visible to x-group

    if (g == 0) {
        const float* by = s + TPA * PAD + lt * PAD;
        double acc = 0.0;
#pragma unroll
        for (int v = 0; v < V; ++v) {
            float d = r[v] - by[v];
            acc += (double)d * (double)d;
        }
#pragma unroll
        for (int off = 16; off; off >>= 1)
            acc += __shfl_down_sync(0xffffffffu, acc, off);
        if ((lt & 31) == 0) wsum[lt >> 5] = acc;
    }
    __syncthreads();
    if (tid == 0)
        g_dist[b][l] = (float)(wsum[0] + wsum[1] + wsum[2] + wsum[3]);
}

// ---------------------------------------------------------------------
// Chain + loss kernel (unchanged)
// ---------------------------------------------------------------------
__global__ void ebsw_chain_kernel(float* __restrict__ out) {
    const int b = threadIdx.x;
    __shared__ double sh[BATCH];
    const float* db = g_dist[b];
    float dist_old = db[0];
    double acc = (double)dist_old;
    for (int l = 1; l < LPROJ; ++l) {
        float dn = db[l];
        float ar = fminf(0.0f, __fadd_rn(dn, -dist_old));
        if (g_logu[l][b] <= ar) dist_old = dn;
        acc += (double)dist_old;
    }
    sh[b] = sqrt(acc / (double)LPROJ);
    __syncthreads();
    if (b == 0) {
        double ssum = 0.0;
        for (int i = 0; i < BATCH; ++i) ssum += sh[i];
        out[0] = (float)(ssum / (double)BATCH);
    }
}

// ---------------------------------------------------------------------
extern "C" void kernel_launch(void* const* d_in, const int* in_sizes, int n_in,
                              void* d_out, int out_size) {
    const float* x = (const float*)d_in[0];
    const float* y = (const float*)d_in[1];
    float* out = (float*)d_out;

    ebsw_rng_kernel<<<LPROJ, BATCH * DIMS>>>();
    ebsw_dist_kernel<<<BATCH * LPROJ, TPB>>>(x, y);
    ebsw_chain_kernel<<<1, BATCH>>>(out);
}

// round 12
// speedup vs baseline: 1.3682x; 1.0298x over previous
#include <cuda_runtime.h>
#include <stdint.h>

// =====================================================================
// EBSW loss: JAX threefry RNG + IMH chain + sliced W2 distances
// R12: R10 network, compact code. Merges k=32..4096 run in ONE runtime
//      loop (runtime shfl/smem distances; compile-time intra-reg tail),
//      shrinking SASS below the I$ plateau. setneg uses FMUL (+/-1) on
//      the idle fma pipe instead of LOP3 XOR on the alu pipe.
// =====================================================================

#define PARTITIONABLE 1

static const int BATCH = 64;
static const int NPTS  = 4096;
static const int DIMS  = 3;
static const int LPROJ = 128;

__device__ float g_theta[LPROJ][BATCH][DIMS];
__device__ float g_logu [LPROJ][BATCH];
__device__ float g_dist [BATCH][LPROJ];

// ---------------------------------------------------------------------
// threefry2x32 (20 rounds)
// ---------------------------------------------------------------------
__device__ __forceinline__ uint2 tf2x32(unsigned k0, unsigned k1,
                                        unsigned x0, unsigned x1) {
    unsigned ks2 = k0 ^ k1 ^ 0x1BD11BDAu;
    x0 += k0; x1 += k1;
#define TFR(r) { x0 += x1; x1 = (x1 << (r)) | (x1 >> (32 - (r))); x1 ^= x0; }
    TFR(13) TFR(15) TFR(26) TFR(6)
    x0 += k1; x1 += ks2 + 1u;
    TFR(17) TFR(29) TFR(16) TFR(24)
    x0 += ks2; x1 += k0 + 2u;
    TFR(13) TFR(15) TFR(26) TFR(6)
    x0 += k0; x1 += k1 + 3u;
    TFR(17) TFR(29) TFR(16) TFR(24)
    x0 += k1; x1 += ks2 + 4u;
    TFR(13) TFR(15) TFR(26) TFR(6)
    x0 += ks2; x1 += k0 + 5u;
#undef TFR
    return make_uint2(x0, x1);
}

__device__ __forceinline__ float xla_erfinv(float x) {
    float xx = __fmul_rn(x, x);
    float w  = -log1pf(-xx);
    float p;
    if (w < 5.0f) {
        w = __fadd_rn(w, -2.5f);
        p = 2.81022636e-08f;
        p = __fadd_rn( 3.43273939e-07f, __fmul_rn(p, w));
        p = __fadd_rn(-3.5233877e-06f,  __fmul_rn(p, w));
        p = __fadd_rn(-4.39150654e-06f, __fmul_rn(p, w));
        p = __fadd_rn( 0.00021858087f,  __fmul_rn(p, w));
        p = __fadd_rn(-0.00125372503f,  __fmul_rn(p, w));
        p = __fadd_rn(-0.00417768164f,  __fmul_rn(p, w));
        p = __fadd_rn( 0.246640727f,    __fmul_rn(p, w));
        p = __fadd_rn( 1.50140941f,     __fmul_rn(p, w));
    } else {
        w = __fadd_rn(__fsqrt_rn(w), -3.0f);
        p = -0.000200214257f;
        p = __fadd_rn( 0.000100950558f, __fmul_rn(p, w));
        p = __fadd_rn( 0.00134934322f,  __fmul_rn(p, w));
        p = __fadd_rn(-0.00367342844f,  __fmul_rn(p, w));
        p = __fadd_rn( 0.00573950773f,  __fmul_rn(p, w));
        p = __fadd_rn(-0.0076224613f,   __fmul_rn(p, w));
        p = __fadd_rn( 0.00943887047f,  __fmul_rn(p, w));
        p = __fadd_rn( 1.00167406f,     __fmul_rn(p, w));
        p = __fadd_rn( 2.83297682f,     __fmul_rn(p, w));
    }
    return __fmul_rn(p, x);
}

__device__ __forceinline__ float bits_to_unit(unsigned bits) {
    return __uint_as_float((bits >> 9) | 0x3f800000u) - 1.0f;
}

// ---------------------------------------------------------------------
// RNG kernel (unchanged — bit-exact, ~5us)
// ---------------------------------------------------------------------
__global__ void ebsw_rng_kernel() {
    const int l = blockIdx.x;
    const int t = threadIdx.x;
    __shared__ float raw[BATCH * DIMS];

    uint2 kl = tf2x32(0u, 42u, 0u, (unsigned)l);
    uint2 ka, kb;
    if (l == 0) {
        ka = kl; kb = make_uint2(0u, 0u);
    } else {
#if PARTITIONABLE
        ka = tf2x32(kl.x, kl.y, 0u, 0u);
        kb = tf2x32(kl.x, kl.y, 0u, 1u);
#else
        uint2 p0 = tf2x32(kl.x, kl.y, 0u, 2u);
        uint2 p1 = tf2x32(kl.x, kl.y, 1u, 3u);
        ka = make_uint2(p0.x, p1.x);
        kb = make_uint2(p0.y, p1.y);
#endif
    }

    unsigned bits;
#if PARTITIONABLE
    { uint2 r = tf2x32(ka.x, ka.y, 0u, (unsigned)t); bits = r.x ^ r.y; }
#else
    if (t < 96) { uint2 r = tf2x32(ka.x, ka.y, (unsigned)t, (unsigned)(96 + t)); bits = r.x; }
    else        { uint2 r = tf2x32(ka.x, ka.y, (unsigned)(t - 96), (unsigned)t); bits = r.y; }
#endif
    const float LO = -0.99999994f;
    float f = bits_to_unit(bits);
    float u = __fadd_rn(__fmul_rn(f, 2.0f), LO);
    u = fmaxf(LO, u);
    raw[t] = __fmul_rn(1.41421356237309515f, xla_erfinv(u));
    __syncthreads();

    if (t < BATCH) {
        float v0 = raw[t * 3 + 0], v1 = raw[t * 3 + 1], v2 = raw[t * 3 + 2];
        float s  = __fadd_rn(__fadd_rn(__fmul_rn(v0, v0), __fmul_rn(v1, v1)),
                             __fmul_rn(v2, v2));
        float r  = __fsqrt_rn(s);
        g_theta[l][t][0] = __fdiv_rn(v0, r);
        g_theta[l][t][1] = __fdiv_rn(v1, r);
        g_theta[l][t][2] = __fdiv_rn(v2, r);

        if (l >= 1) {
            unsigned ub;
#if PARTITIONABLE
            { uint2 r2 = tf2x32(kb.x, kb.y, 0u, (unsigned)t); ub = r2.x ^ r2.y; }
#else
            if (t < 32) { uint2 r2 = tf2x32(kb.x, kb.y, (unsigned)t, (unsigned)(32 + t)); ub = r2.x; }
            else        { uint2 r2 = tf2x32(kb.x, kb.y, (unsigned)(t - 32), (unsigned)t); ub = r2.y; }
#endif
            g_logu[l][t] = logf(bits_to_unit(ub));
        }
    }
}

// ---------------------------------------------------------------------
// Distance kernel: V=32 elems/thread, 128 threads/array, 256 thr/CTA
// ---------------------------------------------------------------------
static const int TPB = 256;
static const int TPA = 128;    // threads per array
static const int V   = 32;     // elements per thread
static const int PAD = 33;     // padded row stride (conflict-free)

// per-group named barrier (128 threads = 4 whole warps)
__device__ __forceinline__ void barg(int id) {
    asm volatile("bar.sync %0, %1;" :: "r"(id), "r"(TPA) : "memory");
}

// fixed ascending compare-exchange: min -> a, max -> b
__device__ __forceinline__ void cxa(float& a, float& b) {
    float mn = fminf(a, b);
    float mx = fmaxf(a, b);
    a = mn; b = mx;
}

// ascending intra-register merge, strides J..1 (compile-time)
template<int J>
__device__ __forceinline__ void merge_reg_asc(float* r) {
    if constexpr (J >= 1) {
#pragma unroll
        for (int v = 0; v < V; ++v)
            if ((v & J) == 0) cxa(r[v], r[v | J]);
        merge_reg_asc<J / 2>(r);
    }
}

// intra-register sort phase, compile-time per-element directions
template<int K, int J>
__device__ __forceinline__ void sort_reg_small(float* r) {
    if constexpr (J >= 1) {
#pragma unroll
        for (int v = 0; v < V; ++v) {
            if ((v & J) == 0) {
                if ((v & K) == 0) cxa(r[v], r[v | J]);
                else              cxa(r[v | J], r[v]);
            }
        }
        sort_reg_small<K, J / 2>(r);
    }
}

// negation state via exact multiply by +/-1 (fma pipe, off the alu path)
__device__ __forceinline__ void setneg(float* r, bool want, bool& cur) {
    float s = (cur != want) ? -1.0f : 1.0f;
#pragma unroll
    for (int v = 0; v < V; ++v) r[v] = __fmul_rn(r[v], s);
    cur = want;
}

__global__ __launch_bounds__(TPB) void ebsw_dist_kernel(
        const float* __restrict__ x, const float* __restrict__ y) {
    __shared__ float s[2 * TPA * PAD];   // staging/exchange, one half per group
    __shared__ double wsum[TPA / 32];
    const int blk = blockIdx.x;
    const int b = blk >> 7;
    const int l = blk & (LPROJ - 1);

    const float t0 = g_theta[l][b][0];
    const float t1 = g_theta[l][b][1];
    const float t2 = g_theta[l][b][2];

    const int tid = threadIdx.x;
    const int g   = tid >> 7;          // 0 -> x array, 1 -> y array
    const int lt  = tid & (TPA - 1);   // 0..127 within group
    const int barid = g + 1;           // named barrier 1 or 2
    float* buf = s + g * (TPA * PAD);

    // Coalesced projection staging (strided->blocked transpose via smem)
    const float* pb = (g == 0 ? x : y) + (size_t)b * NPTS * DIMS;
    for (int n = lt; n < NPTS; n += TPA) {
        int o = n * 3;
        buf[(n >> 5) * PAD + (n & 31)] =
            fmaf(pb[o], t0, fmaf(pb[o + 1], t1, pb[o + 2] * t2));
    }
    barg(barid);

    // Load 32 contiguous elements into registers: i = lt*32 + v
    float r[V];
#pragma unroll
    for (int v = 0; v < V; ++v) r[v] = buf[lt * PAD + v];
    barg(barid);

    // ---- bitonic sort of 4096 = 128 threads x 32 regs ----
    // k = 2..16: compile-time directions via operand swap (unrolled once)
    sort_reg_small<2, 1>(r);
    sort_reg_small<4, 2>(r);
    sort_reg_small<8, 4>(r);
    sort_reg_small<16, 8>(r);

    // k = 32*2^m, m = 0..7: ONE runtime loop (small code footprint).
    // Direction folded into sign negation; all comparators ascending.
    bool neg = false;
#pragma unroll 1
    for (int m = 0; m <= 7; ++m) {
        bool want = (m < 7) && (((lt >> m) & 1) != 0);
        setneg(r, want, neg);
        // cross-thread exchange distances D0 = 2^(m-1) .. 1 (none for m=0)
#pragma unroll 1
        for (int d = (m == 0) ? 0 : (1 << (m - 1)); d >= 1; d >>= 1) {
            const bool keepmin = ((lt & d) == 0);
            if (d >= 32) {
#pragma unroll
                for (int v = 0; v < V; ++v) buf[lt * PAD + v] = r[v];
                barg(barid);
                const int p = (lt ^ d) * PAD;
#pragma unroll
                for (int v = 0; v < V; ++v) {
                    float o = buf[p + v];
                    r[v] = keepmin ? fminf(r[v], o) : fmaxf(r[v], o);
                }
                barg(barid);
            } else {
#pragma unroll
                for (int v = 0; v < V; ++v) {
                    float o = __shfl_xor_sync(0xffffffffu, r[v], d);
                    r[v] = keepmin ? fminf(r[v], o) : fmaxf(r[v], o);
                }
            }
        }
        merge_reg_asc<V / 2>(r);   // intra-register tail (compile-time strides)
    }
    // neg == false here: registers hold exact original values, fully sorted.

    // ---- final reduce: y-group publishes, x-group diffs from registers ----
    if (g == 1) {
#pragma unroll
        for (int v = 0; v < V; ++v) buf[lt * PAD + v] = r[v];
    }
    __syncthreads();   // y sorted values visible to x-group

    if (g == 0) {
        const float* by = s + TPA * PAD + lt * PAD;
        double acc = 0.0;
#pragma unroll
        for (int v = 0; v < V; ++v) {
            float d = r[v] - by[v];
            acc += (double)d * (double)d;
        }
#pragma unroll
        for (int off = 16; off; off >>= 1)
            acc += __shfl_down_sync(0xffffffffu, acc, off);
        if ((lt & 31) == 0) wsum[lt >> 5] = acc;
    }
    __syncthreads();
    if (tid == 0)
        g_dist[b][l] = (float)(wsum[0] + wsum[1] + wsum[2] + wsum[3]);
}

// ---------------------------------------------------------------------
// Chain + loss kernel (unchanged)
// ---------------------------------------------------------------------
__global__ void ebsw_chain_kernel(float* __restrict__ out) {
    const int b = threadIdx.x;
    __shared__ double sh[BATCH];
    const float* db = g_dist[b];
    float dist_old = db[0];
    double acc = (double)dist_old;
    for (int l = 1; l < LPROJ; ++l) {
        float dn = db[l];
        float ar = fminf(0.0f, __fadd_rn(dn, -dist_old));
        if (g_logu[l][b] <= ar) dist_old = dn;
        acc += (double)dist_old;
    }
    sh[b] = sqrt(acc / (double)LPROJ);
    __syncthreads();
    if (b == 0) {
        double ssum = 0.0;
        for (int i = 0; i < BATCH; ++i) ssum += sh[i];
        out[0] = (float)(ssum / (double)BATCH);
    }
}

// ---------------------------------------------------------------------
extern "C" void kernel_launch(void* const* d_in, const int* in_sizes, int n_in,
                              void* d_out, int out_size) {
    const float* x = (const float*)d_in[0];
    const float* y = (const float*)d_in[1];
    float* out = (float*)d_out;

    ebsw_rng_kernel<<<LPROJ, BATCH * DIMS>>>();
    ebsw_dist_kernel<<<BATCH * LPROJ, TPB>>>(x, y);
    ebsw_chain_kernel<<<1, BATCH>>>(out);
}

// round 13
// speedup vs baseline: 1.3874x; 1.0140x over previous
#include <cuda_runtime.h>
#include <stdint.h>

// =====================================================================
// EBSW loss: JAX threefry RNG + IMH chain + sliced W2 distances
// R13: R12 + (a) Batcher odd-even-merge network for the intra-thread
//      32-sort (191 vs 240 comparators; setneg applied first so the
//      sort is direction-free), (b) float4-vectorized projection
//      staging (24 LDG.128 vs 96 scalar LDG per thread).
// =====================================================================

#define PARTITIONABLE 1

static const int BATCH = 64;
static const int NPTS  = 4096;
static const int DIMS  = 3;
static const int LPROJ = 128;

__device__ float g_theta[LPROJ][BATCH][DIMS];
__device__ float g_logu [LPROJ][BATCH];
__device__ float g_dist [BATCH][LPROJ];

// ---------------------------------------------------------------------
// threefry2x32 (20 rounds)
// ---------------------------------------------------------------------
__device__ __forceinline__ uint2 tf2x32(unsigned k0, unsigned k1,
                                        unsigned x0, unsigned x1) {
    unsigned ks2 = k0 ^ k1 ^ 0x1BD11BDAu;
    x0 += k0; x1 += k1;
#define TFR(r) { x0 += x1; x1 = (x1 << (r)) | (x1 >> (32 - (r))); x1 ^= x0; }
    TFR(13) TFR(15) TFR(26) TFR(6)
    x0 += k1; x1 += ks2 + 1u;
    TFR(17) TFR(29) TFR(16) TFR(24)
    x0 += ks2; x1 += k0 + 2u;
    TFR(13) TFR(15) TFR(26) TFR(6)
    x0 += k0; x1 += k1 + 3u;
    TFR(17) TFR(29) TFR(16) TFR(24)
    x0 += k1; x1 += ks2 + 4u;
    TFR(13) TFR(15) TFR(26) TFR(6)
    x0 += ks2; x1 += k0 + 5u;
#undef TFR
    return make_uint2(x0, x1);
}

__device__ __forceinline__ float xla_erfinv(float x) {
    float xx = __fmul_rn(x, x);
    float w  = -log1pf(-xx);
    float p;
    if (w < 5.0f) {
        w = __fadd_rn(w, -2.5f);
        p = 2.81022636e-08f;
        p = __fadd_rn( 3.43273939e-07f, __fmul_rn(p, w));
        p = __fadd_rn(-3.5233877e-06f,  __fmul_rn(p, w));
        p = __fadd_rn(-4.39150654e-06f, __fmul_rn(p, w));
        p = __fadd_rn( 0.00021858087f,  __fmul_rn(p, w));
        p = __fadd_rn(-0.00125372503f,  __fmul_rn(p, w));
        p = __fadd_rn(-0.00417768164f,  __fmul_rn(p, w));
        p = __fadd_rn( 0.246640727f,    __fmul_rn(p, w));
        p = __fadd_rn( 1.50140941f,     __fmul_rn(p, w));
    } else {
        w = __fadd_rn(__fsqrt_rn(w), -3.0f);
        p = -0.000200214257f;
        p = __fadd_rn( 0.000100950558f, __fmul_rn(p, w));
        p = __fadd_rn( 0.00134934322f,  __fmul_rn(p, w));
        p = __fadd_rn(-0.00367342844f,  __fmul_rn(p, w));
        p = __fadd_rn( 0.00573950773f,  __fmul_rn(p, w));
        p = __fadd_rn(-0.0076224613f,   __fmul_rn(p, w));
        p = __fadd_rn( 0.00943887047f,  __fmul_rn(p, w));
        p = __fadd_rn( 1.00167406f,     __fmul_rn(p, w));
        p = __fadd_rn( 2.83297682f,     __fmul_rn(p, w));
    }
    return __fmul_rn(p, x);
}

__device__ __forceinline__ float bits_to_unit(unsigned bits) {
    return __uint_as_float((bits >> 9) | 0x3f800000u) - 1.0f;
}

// ---------------------------------------------------------------------
// RNG kernel (unchanged — bit-exact, ~5us)
// ---------------------------------------------------------------------
__global__ void ebsw_rng_kernel() {
    const int l = blockIdx.x;
    const int t = threadIdx.x;
    __shared__ float raw[BATCH * DIMS];

    uint2 kl = tf2x32(0u, 42u, 0u, (unsigned)l);
    uint2 ka, kb;
    if (l == 0) {
        ka = kl; kb = make_uint2(0u, 0u);
    } else {
#if PARTITIONABLE
        ka = tf2x32(kl.x, kl.y, 0u, 0u);
        kb = tf2x32(kl.x, kl.y, 0u, 1u);
#else
        uint2 p0 = tf2x32(kl.x, kl.y, 0u, 2u);
        uint2 p1 = tf2x32(kl.x, kl.y, 1u, 3u);
        ka = make_uint2(p0.x, p1.x);
        kb = make_uint2(p0.y, p1.y);
#endif
    }

    unsigned bits;
#if PARTITIONABLE
    { uint2 r = tf2x32(ka.x, ka.y, 0u, (unsigned)t); bits = r.x ^ r.y; }
#else
    if (t < 96) { uint2 r = tf2x32(ka.x, ka.y, (unsigned)t, (unsigned)(96 + t)); bits = r.x; }
    else        { uint2 r = tf2x32(ka.x, ka.y, (unsigned)(t - 96), (unsigned)t); bits = r.y; }
#endif
    const float LO = -0.99999994f;
    float f = bits_to_unit(bits);
    float u = __fadd_rn(__fmul_rn(f, 2.0f), LO);
    u = fmaxf(LO, u);
    raw[t] = __fmul_rn(1.41421356237309515f, xla_erfinv(u));
    __syncthreads();

    if (t < BATCH) {
        float v0 = raw[t * 3 + 0], v1 = raw[t * 3 + 1], v2 = raw[t * 3 + 2];
        float s  = __fadd_rn(__fadd_rn(__fmul_rn(v0, v0), __fmul_rn(v1, v1)),
                             __fmul_rn(v2, v2));
        float r  = __fsqrt_rn(s);
        g_theta[l][t][0] = __fdiv_rn(v0, r);
        g_theta[l][t][1] = __fdiv_rn(v1, r);
        g_theta[l][t][2] = __fdiv_rn(v2, r);

        if (l >= 1) {
            unsigned ub;
#if PARTITIONABLE
            { uint2 r2 = tf2x32(kb.x, kb.y, 0u, (unsigned)t); ub = r2.x ^ r2.y; }
#else
            if (t < 32) { uint2 r2 = tf2x32(kb.x, kb.y, (unsigned)t, (unsigned)(32 + t)); ub = r2.x; }
            else        { uint2 r2 = tf2x32(kb.x, kb.y, (unsigned)(t - 32), (unsigned)t); ub = r2.y; }
#endif
            g_logu[l][t] = logf(bits_to_unit(ub));
        }
    }
}

// ---------------------------------------------------------------------
// Distance kernel: V=32 elems/thread, 128 threads/array, 256 thr/CTA
// ---------------------------------------------------------------------
static const int TPB = 256;
static const int TPA = 128;    // threads per array
static const int V   = 32;     // elements per thread
static const int PAD = 33;     // padded row stride (conflict-free)

// per-group named barrier (128 threads = 4 whole warps)
__device__ __forceinline__ void barg(int id) {
    asm volatile("bar.sync %0, %1;" :: "r"(id), "r"(TPA) : "memory");
}

// fixed ascending compare-exchange: min -> a, max -> b
__device__ __forceinline__ void cxa(float& a, float& b) {
    float mn = fminf(a, b);
    float mx = fmaxf(a, b);
    a = mn; b = mx;
}

// ---- Batcher odd-even merge sort (compile-time, ascending) ----
template<int I, int END, int M, int R>
__device__ __forceinline__ void oem_cmploop(float* r) {
    if constexpr (I + R < END) {
        cxa(r[I], r[I + R]);
        oem_cmploop<I + M, END, M, R>(r);
    }
}

template<int LO, int N, int R>
__device__ __forceinline__ void oem_merge(float* r) {
    if constexpr (2 * R < N) {
        oem_merge<LO, N, 2 * R>(r);
        oem_merge<LO + R, N, 2 * R>(r);
        oem_cmploop<LO + R, LO + N, 2 * R, R>(r);
    } else {
        cxa(r[LO], r[LO + R]);
    }
}

template<int LO, int N>
__device__ __forceinline__ void oem_sort(float* r) {
    if constexpr (N > 1) {
        oem_sort<LO, N / 2>(r);
        oem_sort<LO + N / 2, N / 2>(r);
        oem_merge<LO, N, 1>(r);
    }
}

// ascending intra-register bitonic merge, strides J..1 (compile-time)
template<int J>
__device__ __forceinline__ void merge_reg_asc(float* r) {
    if constexpr (J >= 1) {
#pragma unroll
        for (int v = 0; v < V; ++v)
            if ((v & J) == 0) cxa(r[v], r[v | J]);
        merge_reg_asc<J / 2>(r);
    }
}

// negation state via exact multiply by +/-1 (fma pipe, off the alu path)
__device__ __forceinline__ void setneg(float* r, bool want, bool& cur) {
    float s = (cur != want) ? -1.0f : 1.0f;
#pragma unroll
    for (int v = 0; v < V; ++v) r[v] = __fmul_rn(r[v], s);
    cur = want;
}

__global__ __launch_bounds__(TPB) void ebsw_dist_kernel(
        const float* __restrict__ x, const float* __restrict__ y) {
    __shared__ float s[2 * TPA * PAD];   // staging/exchange, one half per group
    __shared__ double wsum[TPA / 32];
    const int blk = blockIdx.x;
    const int b = blk >> 7;
    const int l = blk & (LPROJ - 1);

    const float t0 = g_theta[l][b][0];
    const float t1 = g_theta[l][b][1];
    const float t2 = g_theta[l][b][2];

    const int tid = threadIdx.x;
    const int g   = tid >> 7;          // 0 -> x array, 1 -> y array
    const int lt  = tid & (TPA - 1);   // 0..127 within group
    const int barid = g + 1;           // named barrier 1 or 2
    float* buf = s + g * (TPA * PAD);

    // Vectorized coalesced staging: each thread projects 4-point quads
    // (3 float4 = 12 floats per quad), same fmaf ordering as before.
    const float* pb = (g == 0 ? x : y) + (size_t)b * NPTS * DIMS;
    for (int q = lt; q < NPTS / 4; q += TPA) {
        const float4* p4 = (const float4*)(pb + (size_t)q * 12);
        float4 a = p4[0], bb = p4[1], c = p4[2];
        float p0 = fmaf(a.x,  t0, fmaf(a.y,  t1, a.z  * t2));
        float p1 = fmaf(a.w,  t0, fmaf(bb.x, t1, bb.y * t2));
        float p2 = fmaf(bb.z, t0, fmaf(bb.w, t1, c.x  * t2));
        float p3 = fmaf(c.y,  t0, fmaf(c.z,  t1, c.w  * t2));
        int n0 = q * 4;                       // n0 % 4 == 0 -> same padded row
        float* row = buf + (n0 >> 5) * PAD + (n0 & 31);
        row[0] = p0; row[1] = p1; row[2] = p2; row[3] = p3;
    }
    barg(barid);

    // Load 32 contiguous elements into registers: i = lt*32 + v
    float r[V];
#pragma unroll
    for (int v = 0; v < V; ++v) r[v] = buf[lt * PAD + v];
    barg(barid);

    // ---- bitonic sort of 4096 = 128 threads x 32 regs ----
    // Intra-thread 32-sort: negate first (per lt bit 0), then Batcher
    // OEM ascending network (191 comparators). End state identical to
    // the bitonic k=2..32 phases: sorted ascending in negated space.
    bool neg = false;
    setneg(r, (lt & 1) != 0, neg);
    oem_sort<0, V>(r);

    // k = 32*2^m, m = 1..7: runtime loop, direction via sign negation.
    #pragma unroll 1
    for (int m = 1; m <= 7; ++m) {
        bool want = (m < 7) && (((lt >> m) & 1) != 0);
        setneg(r, want, neg);
        // cross-thread exchange distances 2^(m-1) .. 1
#pragma unroll 1
        for (int d = 1 << (m - 1); d >= 1; d >>= 1) {
            const bool keepmin = ((lt & d) == 0);
            if (d >= 32) {
#pragma unroll
                for (int v = 0; v < V; ++v) buf[lt * PAD + v] = r[v];
                barg(barid);
                const int p = (lt ^ d) * PAD;
#pragma unroll
                for (int v = 0; v < V; ++v) {
                    float o = buf[p + v];
                    r[v] = keepmin ? fminf(r[v], o) : fmaxf(r[v], o);
                }
                barg(barid);
            } else {
#pragma unroll
                for (int v = 0; v < V; ++v) {
                    float o = __shfl_xor_sync(0xffffffffu, r[v], d);
                    r[v] = keepmin ? fminf(r[v], o) : fmaxf(r[v], o);
                }
            }
        }
        merge_reg_asc<V / 2>(r);   // intra-register bitonic tail
    }
    // neg == false here: registers hold exact original values, fully sorted.

    // ---- final reduce: y-group publishes, x-group diffs from registers ----
    if (g == 1) {
#pragma unroll
        for (int v = 0; v < V; ++v) buf[lt * PAD + v] = r[v];
    }
    __syncthreads();   // y sorted values visible to x-group

    if (g == 0) {
        const float* by = s + TPA * PAD + lt * PAD;
        double acc = 0.0;
#pragma unroll
        for (int v = 0; v < V; ++v) {
            float d = r[v] - by[v];
            acc += (double)d * (double)d;
        }
#pragma unroll
        for (int off = 16; off; off >>= 1)
            acc += __shfl_down_sync(0xffffffffu, acc, off);
        if ((lt & 31) == 0) wsum[lt >> 5] = acc;
    }
    __syncthreads();
    if (tid == 0)
        g_dist[b][l] = (float)(wsum[0] + wsum[1] + wsum[2] + wsum[3]);
}

// ---------------------------------------------------------------------
// Chain + loss kernel (unchanged)
// ---------------------------------------------------------------------
__global__ void ebsw_chain_kernel(float* __restrict__ out) {
    const int b = threadIdx.x;
    __shared__ double sh[BATCH];
    const float* db = g_dist[b];
    float dist_old = db[0];
    double acc = (double)dist_old;
    for (int l = 1; l < LPROJ; ++l) {
        float dn = db[l];
        float ar = fminf(0.0f, __fadd_rn(dn, -dist_old));
        if (g_logu[l][b] <= ar) dist_old = dn;
        acc += (double)dist_old;
    }
    sh[b] = sqrt(acc / (double)LPROJ);
    __syncthreads();
    if (b == 0) {
        double ssum = 0.0;
        for (int i = 0; i < BATCH; ++i) ssum += sh[i];
        out[0] = (float)(ssum / (double)BATCH);
    }
}

// ---------------------------------------------------------------------
extern "C" void kernel_launch(void* const* d_in, const int* in_sizes, int n_in,
                              void* d_out, int out_size) {
    const float* x = (const float*)d_in[0];
    const float* y = (const float*)d_in[1];
    float* out = (float*)d_out;

    ebsw_rng_kernel<<<LPROJ, BATCH * DIMS>>>();
    ebsw_dist_kernel<<<BATCH * LPROJ, TPB>>>(x, y);
    ebsw_chain_kernel<<<1, BATCH>>>(out);
}

// round 14
// speedup vs baseline: 1.4176x; 1.0218x over previous
#include <cuda_runtime.h>
#include <stdint.h>

// =====================================================================
// EBSW loss: JAX threefry RNG + IMH chain + sliced W2 distances
// R14: R13 + float pairwise-tree reduce (removes the fp64 DFMA/F2F
//      tail from every CTA; double kept only for the final 4-way sum).
// =====================================================================

#define PARTITIONABLE 1

static const int BATCH = 64;
static const int NPTS  = 4096;
static const int DIMS  = 3;
static const int LPROJ = 128;

__device__ float g_theta[LPROJ][BATCH][DIMS];
__device__ float g_logu [LPROJ][BATCH];
__device__ float g_dist [BATCH][LPROJ];

// ---------------------------------------------------------------------
// threefry2x32 (20 rounds)
// ---------------------------------------------------------------------
__device__ __forceinline__ uint2 tf2x32(unsigned k0, unsigned k1,
                                        unsigned x0, unsigned x1) {
    unsigned ks2 = k0 ^ k1 ^ 0x1BD11BDAu;
    x0 += k0; x1 += k1;
#define TFR(r) { x0 += x1; x1 = (x1 << (r)) | (x1 >> (32 - (r))); x1 ^= x0; }
    TFR(13) TFR(15) TFR(26) TFR(6)
    x0 += k1; x1 += ks2 + 1u;
    TFR(17) TFR(29) TFR(16) TFR(24)
    x0 += ks2; x1 += k0 + 2u;
    TFR(13) TFR(15) TFR(26) TFR(6)
    x0 += k0; x1 += k1 + 3u;
    TFR(17) TFR(29) TFR(16) TFR(24)
    x0 += k1; x1 += ks2 + 4u;
    TFR(13) TFR(15) TFR(26) TFR(6)
    x0 += ks2; x1 += k0 + 5u;
#undef TFR
    return make_uint2(x0, x1);
}

__device__ __forceinline__ float xla_erfinv(float x) {
    float xx = __fmul_rn(x, x);
    float w  = -log1pf(-xx);
    float p;
    if (w < 5.0f) {
        w = __fadd_rn(w, -2.5f);
        p = 2.81022636e-08f;
        p = __fadd_rn( 3.43273939e-07f, __fmul_rn(p, w));
        p = __fadd_rn(-3.5233877e-06f,  __fmul_rn(p, w));
        p = __fadd_rn(-4.39150654e-06f, __fmul_rn(p, w));
        p = __fadd_rn( 0.00021858087f,  __fmul_rn(p, w));
        p = __fadd_rn(-0.00125372503f,  __fmul_rn(p, w));
        p = __fadd_rn(-0.00417768164f,  __fmul_rn(p, w));
        p = __fadd_rn( 0.246640727f,    __fmul_rn(p, w));
        p = __fadd_rn( 1.50140941f,     __fmul_rn(p, w));
    } else {
        w = __fadd_rn(__fsqrt_rn(w), -3.0f);
        p = -0.000200214257f;
        p = __fadd_rn( 0.000100950558f, __fmul_rn(p, w));
        p = __fadd_rn( 0.00134934322f,  __fmul_rn(p, w));
        p = __fadd_rn(-0.00367342844f,  __fmul_rn(p, w));
        p = __fadd_rn( 0.00573950773f,  __fmul_rn(p, w));
        p = __fadd_rn(-0.0076224613f,   __fmul_rn(p, w));
        p = __fadd_rn( 0.00943887047f,  __fmul_rn(p, w));
        p = __fadd_rn( 1.00167406f,     __fmul_rn(p, w));
        p = __fadd_rn( 2.83297682f,     __fmul_rn(p, w));
    }
    return __fmul_rn(p, x);
}

__device__ __forceinline__ float bits_to_unit(unsigned bits) {
    return __uint_as_float((bits >> 9) | 0x3f800000u) - 1.0f;
}

// ---------------------------------------------------------------------
// RNG kernel (unchanged — bit-exact, ~5us)
// ---------------------------------------------------------------------
__global__ void ebsw_rng_kernel() {
    const int l = blockIdx.x;
    const int t = threadIdx.x;
    __shared__ float raw[BATCH * DIMS];

    uint2 kl = tf2x32(0u, 42u, 0u, (unsigned)l);
    uint2 ka, kb;
    if (l == 0) {
        ka = kl; kb = make_uint2(0u, 0u);
    } else {
#if PARTITIONABLE
        ka = tf2x32(kl.x, kl.y, 0u, 0u);
        kb = tf2x32(kl.x, kl.y, 0u, 1u);
#else
        uint2 p0 = tf2x32(kl.x, kl.y, 0u, 2u);
        uint2 p1 = tf2x32(kl.x, kl.y, 1u, 3u);
        ka = make_uint2(p0.x, p1.x);
        kb = make_uint2(p0.y, p1.y);
#endif
    }

    unsigned bits;
#if PARTITIONABLE
    { uint2 r = tf2x32(ka.x, ka.y, 0u, (unsigned)t); bits = r.x ^ r.y; }
#else
    if (t < 96) { uint2 r = tf2x32(ka.x, ka.y, (unsigned)t, (unsigned)(96 + t)); bits = r.x; }
    else        { uint2 r = tf2x32(ka.x, ka.y, (unsigned)(t - 96), (unsigned)t); bits = r.y; }
#endif
    const float LO = -0.99999994f;
    float f = bits_to_unit(bits);
    float u = __fadd_rn(__fmul_rn(f, 2.0f), LO);
    u = fmaxf(LO, u);
    raw[t] = __fmul_rn(1.41421356237309515f, xla_erfinv(u));
    __syncthreads();

    if (t < BATCH) {
        float v0 = raw[t * 3 + 0], v1 = raw[t * 3 + 1], v2 = raw[t * 3 + 2];
        float s  = __fadd_rn(__fadd_rn(__fmul_rn(v0, v0), __fmul_rn(v1, v1)),
                             __fmul_rn(v2, v2));
        float r  = __fsqrt_rn(s);
        g_theta[l][t][0] = __fdiv_rn(v0, r);
        g_theta[l][t][1] = __fdiv_rn(v1, r);
        g_theta[l][t][2] = __fdiv_rn(v2, r);

        if (l >= 1) {
            unsigned ub;
#if PARTITIONABLE
            { uint2 r2 = tf2x32(kb.x, kb.y, 0u, (unsigned)t); ub = r2.x ^ r2.y; }
#else
            if (t < 32) { uint2 r2 = tf2x32(kb.x, kb.y, (unsigned)t, (unsigned)(32 + t)); ub = r2.x; }
            else        { uint2 r2 = tf2x32(kb.x, kb.y, (unsigned)(t - 32), (unsigned)t); ub = r2.y; }
#endif
            g_logu[l][t] = logf(bits_to_unit(ub));
        }
    }
}

// ---------------------------------------------------------------------
// Distance kernel: V=32 elems/thread, 128 threads/array, 256 thr/CTA
// ---------------------------------------------------------------------
static const int TPB = 256;
static const int TPA = 128;    // threads per array
static const int V   = 32;     // elements per thread
static const int PAD = 33;     // padded row stride (conflict-free)

// per-group named barrier (128 threads = 4 whole warps)
__device__ __forceinline__ void barg(int id) {
    asm volatile("bar.sync %0, %1;" :: "r"(id), "r"(TPA) : "memory");
}

// fixed ascending compare-exchange: min -> a, max -> b
__device__ __forceinline__ void cxa(float& a, float& b) {
    float mn = fminf(a, b);
    float mx = fmaxf(a, b);
    a = mn; b = mx;
}

// ---- Batcher odd-even merge sort (compile-time, ascending) ----
template<int I, int END, int M, int R>
__device__ __forceinline__ void oem_cmploop(float* r) {
    if constexpr (I + R < END) {
        cxa(r[I], r[I + R]);
        oem_cmploop<I + M, END, M, R>(r);
    }
}

template<int LO, int N, int R>
__device__ __forceinline__ void oem_merge(float* r) {
    if constexpr (2 * R < N) {
        oem_merge<LO, N, 2 * R>(r);
        oem_merge<LO + R, N, 2 * R>(r);
        oem_cmploop<LO + R, LO + N, 2 * R, R>(r);
    } else {
        cxa(r[LO], r[LO + R]);
    }
}

template<int LO, int N>
__device__ __forceinline__ void oem_sort(float* r) {
    if constexpr (N > 1) {
        oem_sort<LO, N / 2>(r);
        oem_sort<LO + N / 2, N / 2>(r);
        oem_merge<LO, N, 1>(r);
    }
}

// ascending intra-register bitonic merge, strides J..1 (compile-time)
template<int J>
__device__ __forceinline__ void merge_reg_asc(float* r) {
    if constexpr (J >= 1) {
#pragma unroll
        for (int v = 0; v < V; ++v)
            if ((v & J) == 0) cxa(r[v], r[v | J]);
        merge_reg_asc<J / 2>(r);
    }
}

// negation state via exact multiply by +/-1 (fma pipe, off the alu path)
__device__ __forceinline__ void setneg(float* r, bool want, bool& cur) {
    float s = (cur != want) ? -1.0f : 1.0f;
#pragma unroll
    for (int v = 0; v < V; ++v) r[v] = __fmul_rn(r[v], s);
    cur = want;
}

__global__ __launch_bounds__(TPB) void ebsw_dist_kernel(
        const float* __restrict__ x, const float* __restrict__ y) {
    __shared__ float s[2 * TPA * PAD];   // staging/exchange, one half per group
    __shared__ double wsum[TPA / 32];
    const int blk = blockIdx.x;
    const int b = blk >> 7;
    const int l = blk & (LPROJ - 1);

    const float t0 = g_theta[l][b][0];
    const float t1 = g_theta[l][b][1];
    const float t2 = g_theta[l][b][2];

    const int tid = threadIdx.x;
    const int g   = tid >> 7;          // 0 -> x array, 1 -> y array
    const int lt  = tid & (TPA - 1);   // 0..127 within group
    const int barid = g + 1;           // named barrier 1 or 2
    float* buf = s + g * (TPA * PAD);

    // Vectorized coalesced staging: each thread projects 4-point quads
    // (3 float4 = 12 floats per quad), same fmaf ordering as before.
    const float* pb = (g == 0 ? x : y) + (size_t)b * NPTS * DIMS;
    for (int q = lt; q < NPTS / 4; q += TPA) {
        const float4* p4 = (const float4*)(pb + (size_t)q * 12);
        float4 a = p4[0], bb = p4[1], c = p4[2];
        float p0 = fmaf(a.x,  t0, fmaf(a.y,  t1, a.z  * t2));
        float p1 = fmaf(a.w,  t0, fmaf(bb.x, t1, bb.y * t2));
        float p2 = fmaf(bb.z, t0, fmaf(bb.w, t1, c.x  * t2));
        float p3 = fmaf(c.y,  t0, fmaf(c.z,  t1, c.w  * t2));
        int n0 = q * 4;                       // n0 % 4 == 0 -> same padded row
        float* row = buf + (n0 >> 5) * PAD + (n0 & 31);
        row[0] = p0; row[1] = p1; row[2] = p2; row[3] = p3;
    }
    barg(barid);

    // Load 32 contiguous elements into registers: i = lt*32 + v
    float r[V];
#pragma unroll
    for (int v = 0; v < V; ++v) r[v] = buf[lt * PAD + v];
    barg(barid);

    // ---- bitonic sort of 4096 = 128 threads x 32 regs ----
    // Intra-thread 32-sort: negate first (per lt bit 0), then Batcher
    // OEM ascending network (191 comparators).
    bool neg = false;
    setneg(r, (lt & 1) != 0, neg);
    oem_sort<0, V>(r);

    // k = 32*2^m, m = 1..7: runtime loop, direction via sign negation.
    #pragma unroll 1
    for (int m = 1; m <= 7; ++m) {
        bool want = (m < 7) && (((lt >> m) & 1) != 0);
        setneg(r, want, neg);
        // cross-thread exchange distances 2^(m-1) .. 1
#pragma unroll 1
        for (int d = 1 << (m - 1); d >= 1; d >>= 1) {
            const bool keepmin = ((lt & d) == 0);
            if (d >= 32) {
#pragma unroll
                for (int v = 0; v < V; ++v) buf[lt * PAD + v] = r[v];
                barg(barid);
                const int p = (lt ^ d) * PAD;
#pragma unroll
                for (int v = 0; v < V; ++v) {
                    float o = buf[p + v];
                    r[v] = keepmin ? fminf(r[v], o) : fmaxf(r[v], o);
                }
                barg(barid);
            } else {
#pragma unroll
                for (int v = 0; v < V; ++v) {
                    float o = __shfl_xor_sync(0xffffffffu, r[v], d);
                    r[v] = keepmin ? fminf(r[v], o) : fmaxf(r[v], o);
                }
            }
        }
        merge_reg_asc<V / 2>(r);   // intra-register bitonic tail
    }
    // neg == false here: registers hold exact original values, fully sorted.

    // ---- final reduce: y-group publishes, x-group diffs from registers ----
    if (g == 1) {
#pragma unroll
        for (int v = 0; v < V; ++v) buf[lt * PAD + v] = r[v];
    }
    __syncthreads();   // y sorted values visible to x-group

    if (g == 0) {
        const float* by = s + TPA * PAD + lt * PAD;
        // float pairwise tree (fma pipe): squares then halving reduction
        float sq[V];
#pragma unroll
        for (int v = 0; v < V; ++v) {
            float d = r[v] - by[v];
            sq[v] = __fmul_rn(d, d);
        }
#pragma unroll
        for (int st = V / 2; st >= 1; st >>= 1) {
#pragma unroll
            for (int v = 0; v < st; ++v) sq[v] = __fadd_rn(sq[v], sq[v + st]);
        }
        float acc = sq[0];
#pragma unroll
        for (int off = 16; off; off >>= 1)
            acc = __fadd_rn(acc, __shfl_down_sync(0xffffffffu, acc, off));
        if ((lt & 31) == 0) wsum[lt >> 5] = (double)acc;
    }
    __syncthreads();
    if (tid == 0)
        g_dist[b][l] = (float)(wsum[0] + wsum[1] + wsum[2] + wsum[3]);
}

// ---------------------------------------------------------------------
// Chain + loss kernel (unchanged)
// ---------------------------------------------------------------------
__global__ void ebsw_chain_kernel(float* __restrict__ out) {
    const int b = threadIdx.x;
    __shared__ double sh[BATCH];
    const float* db = g_dist[b];
    float dist_old = db[0];
    double acc = (double)dist_old;
    for (int l = 1; l < LPROJ; ++l) {
        float dn = db[l];
        float ar = fminf(0.0f, __fadd_rn(dn, -dist_old));
        if (g_logu[l][b] <= ar) dist_old = dn;
        acc += (double)dist_old;
    }
    sh[b] = sqrt(acc / (double)LPROJ);
    __syncthreads();
    if (b == 0) {
        double ssum = 0.0;
        for (int i = 0; i < BATCH; ++i) ssum += sh[i];
        out[0] = (float)(ssum / (double)BATCH);
    }
}

// ---------------------------------------------------------------------
extern "C" void kernel_launch(void* const* d_in, const int* in_sizes, int n_in,
                              void* d_out, int out_size) {
    const float* x = (const float*)d_in[0];
    const float* y = (const float*)d_in[1];
    float* out = (float*)d_out;

    ebsw_rng_kernel<<<LPROJ, BATCH * DIMS>>>();
    ebsw_dist_kernel<<<BATCH * LPROJ, TPB>>>(x, y);
    ebsw_chain_kernel<<<1, BATCH>>>(out);
}